// round 2
// baseline (speedup 1.0000x reference)
#include <cuda_runtime.h>
#include <math.h>

#define BB 2
#define LL 2048
#define HID 4096
#define NH 32
#define HD 128
#define MM (BB*LL)           // 4096 tokens
#define QKVN (3*HID)         // 12288
#define BH (BB*NH)           // 64
#define SCALE 0.08838834764831845f   // 1/sqrt(128)

// -------- scratch (static device globals; allocation-free) --------
__device__ float g_q[(size_t)BH*LL*HD];        // [B,NH,L,D] 64MB
__device__ float g_k[(size_t)BH*LL*HD];        // 64MB
__device__ float g_v[(size_t)BH*LL*HD];        // 64MB
__device__ float g_ctx[(size_t)MM*HID];        // [B,L,H]   64MB
__device__ int   g_vm[MM];
__device__ float g_cos[LL*HD];
__device__ float g_sin[LL*HD];

// -------- prep: vision mask + RoPE tables --------
__global__ void prep_kernel(const int* __restrict__ tt) {
    int idx = blockIdx.x * blockDim.x + threadIdx.x;   // 0..262143
    if (idx < MM) {
        int l = idx & (LL - 1);
        g_vm[idx] = (l < LL - 1) && (tt[idx] == 1) && (tt[idx + 1] == 1);
    }
    if (idx < LL * HD) {
        int p = idx / HD;
        int d = idx & (HD - 1);
        int j = d & 63;
        double inv = exp(-log(10000.0) * (double)(2 * j) / 128.0);
        double ang = (double)p * inv;
        g_cos[idx] = (float)cos(ang);
        g_sin[idx] = (float)sin(ang);
    }
}

// -------- routed QKV GEMM: C[m,n] = sum_k A[m,k] * Wsel(m)[n,k] --------
__global__ void qkv_gemm(const float* __restrict__ A,
                         const float* __restrict__ Wv,
                         const float* __restrict__ Wl) {
    __shared__ float As[16][65];
    __shared__ __align__(16) float Bv[16][64];
    __shared__ __align__(16) float Bl[16][64];
    const int n0 = blockIdx.x * 64;
    const int m0 = blockIdx.y * 64;
    const int t  = threadIdx.x;
    const int tn = (t & 15) * 4;
    const int tm = (t >> 4) * 4;
    const int lm = t >> 2;
    const int lk = (t & 3) * 4;

    bool msk[4];
#pragma unroll
    for (int i = 0; i < 4; i++) msk[i] = (g_vm[m0 + tm + i] != 0);

    float acc[4][4] = {};
    for (int k0 = 0; k0 < HID; k0 += 16) {
        float4 a4 = *(const float4*)(A  + (size_t)(m0 + lm) * HID + k0 + lk);
        float4 v4 = *(const float4*)(Wv + (size_t)(n0 + lm) * HID + k0 + lk);
        float4 l4 = *(const float4*)(Wl + (size_t)(n0 + lm) * HID + k0 + lk);
        As[lk+0][lm] = a4.x; As[lk+1][lm] = a4.y; As[lk+2][lm] = a4.z; As[lk+3][lm] = a4.w;
        Bv[lk+0][lm] = v4.x; Bv[lk+1][lm] = v4.y; Bv[lk+2][lm] = v4.z; Bv[lk+3][lm] = v4.w;
        Bl[lk+0][lm] = l4.x; Bl[lk+1][lm] = l4.y; Bl[lk+2][lm] = l4.z; Bl[lk+3][lm] = l4.w;
        __syncthreads();
#pragma unroll
        for (int k = 0; k < 16; k++) {
            float a[4];
#pragma unroll
            for (int i = 0; i < 4; i++) a[i] = As[k][tm + i];
            float4 wv = *(const float4*)&Bv[k][tn];
            float4 wl = *(const float4*)&Bl[k][tn];
#pragma unroll
            for (int i = 0; i < 4; i++) {
                float w0 = msk[i] ? wv.x : wl.x;
                float w1 = msk[i] ? wv.y : wl.y;
                float w2 = msk[i] ? wv.z : wl.z;
                float w3 = msk[i] ? wv.w : wl.w;
                acc[i][0] += a[i] * w0;
                acc[i][1] += a[i] * w1;
                acc[i][2] += a[i] * w2;
                acc[i][3] += a[i] * w3;
            }
        }
        __syncthreads();
    }
#pragma unroll
    for (int i = 0; i < 4; i++) {
        int m = m0 + tm + i;
        int b = m >> 11;
        int l = m & (LL - 1);
#pragma unroll
        for (int j = 0; j < 4; j++) {
            int n = n0 + tn + j;
            int part = n >> 12;
            int rem  = n & 4095;
            int head = rem >> 7;
            int d    = rem & 127;
            float* dst = (part == 0) ? g_q : ((part == 1) ? g_k : g_v);
            dst[((size_t)(b * NH + head) * LL + l) * HD + d] = acc[i][j];
        }
    }
}

// -------- RoPE in-place on g_q, g_k --------
__global__ void rope_kernel(const int* __restrict__ pos_ids) {
    int blk = blockIdx.x;            // bh*L + l
    int l  = blk & (LL - 1);
    int bh = blk >> 11;
    int b  = bh >> 5;
    int d  = threadIdx.x;            // 0..127
    int p  = pos_ids[b * LL + l];
    if (p < 0) p = 0;
    if (p >= LL) p = LL - 1;
    size_t base = ((size_t)bh * LL + l) * HD;
    float c = g_cos[p * HD + d];
    float s = g_sin[p * HD + d];
    int pd = (d < 64) ? d + 64 : d - 64;
    float q0 = g_q[base + d], qp = g_q[base + pd];
    float k0 = g_k[base + d], kp = g_k[base + pd];
    float qr = (d < 64) ? -qp : qp;
    float kr = (d < 64) ? -kp : kp;
    __syncthreads();
    g_q[base + d] = q0 * c + qr * s;
    g_k[base + d] = k0 * c + kr * s;
}

// -------- fused flash attention (fp32, online softmax) --------
// block = 256 threads, one (bh, 64-row q-tile). K/V tiles of 64 tokens.
// smem: Qs[64][128], Kt[128][68] (transposed), Vs[64][128], Ps[64][68]
#define KT_S 68
#define PS_S 68
#define SM_QS 0
#define SM_KT (64*128)
#define SM_VS (SM_KT + 128*KT_S)
#define SM_PS (SM_VS + 64*128)
#define SM_TOT (SM_PS + 64*PS_S)      // 29440 floats = 117760 bytes

__global__ void flash_attn() {
    extern __shared__ float sm[];
    float* Qs = sm + SM_QS;
    float* Kt = sm + SM_KT;
    float* Vs = sm + SM_VS;
    float* Ps = sm + SM_PS;

    const int bh = blockIdx.y;
    const int m0 = blockIdx.x * 64;
    const float* Q = g_q + (size_t)bh * LL * HD;
    const float* K = g_k + (size_t)bh * LL * HD;
    const float* V = g_v + (size_t)bh * LL * HD;

    const int t = threadIdx.x;
    const int row_l = t >> 2;         // 0..63 (load row)
    const int kb4   = (t & 3) * 4;    // k offset for loads
    const int tm = (t >> 4) * 4;      // score rows tm..tm+3
    const int tc = t & 15;            // score cols 4*tc..4*tc+3 ; O cols 4*tc & 64+4*tc

    // load Q tile
#pragma unroll
    for (int it = 0; it < 8; it++) {
        int k = kb4 + it * 16;
        *(float4*)&Qs[row_l * 128 + k] = *(const float4*)&Q[(size_t)(m0 + row_l) * HD + k];
    }

    float o[4][8];
    float mrow[4], srow[4];
#pragma unroll
    for (int i = 0; i < 4; i++) {
        mrow[i] = -1e30f; srow[i] = 0.f;
#pragma unroll
        for (int j = 0; j < 8; j++) o[i][j] = 0.f;
    }

    for (int j0 = 0; j0 < LL; j0 += 64) {
        __syncthreads();   // prev-iter reads of Kt/Vs/Ps done
        // load K (transposed) and V tiles
#pragma unroll
        for (int it = 0; it < 8; it++) {
            int k = kb4 + it * 16;
            float4 kv = *(const float4*)&K[(size_t)(j0 + row_l) * HD + k];
            Kt[(k + 0) * KT_S + row_l] = kv.x;
            Kt[(k + 1) * KT_S + row_l] = kv.y;
            Kt[(k + 2) * KT_S + row_l] = kv.z;
            Kt[(k + 3) * KT_S + row_l] = kv.w;
            *(float4*)&Vs[row_l * 128 + k] = *(const float4*)&V[(size_t)(j0 + row_l) * HD + k];
        }
        __syncthreads();

        // S = scale * Q K^T  (4x4 per thread)
        float s4[4][4] = {};
#pragma unroll 8
        for (int k = 0; k < 128; k += 4) {
            float qv[4][4], kv[4][4];
#pragma unroll
            for (int i = 0; i < 4; i++)
                *(float4*)qv[i] = *(const float4*)&Qs[(tm + i) * 128 + k];
#pragma unroll
            for (int kk = 0; kk < 4; kk++)
                *(float4*)kv[kk] = *(const float4*)&Kt[(k + kk) * KT_S + 4 * tc];
#pragma unroll
            for (int kk = 0; kk < 4; kk++)
#pragma unroll
                for (int i = 0; i < 4; i++)
#pragma unroll
                    for (int j = 0; j < 4; j++)
                        s4[i][j] += qv[i][kk] * kv[kk][j];
        }

        // online softmax update
#pragma unroll
        for (int i = 0; i < 4; i++) {
            float tmax = s4[i][0];
#pragma unroll
            for (int j = 1; j < 4; j++) tmax = fmaxf(tmax, s4[i][j]);
#pragma unroll
            for (int msk_ = 1; msk_ < 16; msk_ <<= 1)
                tmax = fmaxf(tmax, __shfl_xor_sync(0xffffffffu, tmax, msk_));
            tmax *= SCALE;
            float mnew = fmaxf(mrow[i], tmax);
            float fac  = __expf(mrow[i] - mnew);
            mrow[i] = mnew;
            float psum = 0.f;
#pragma unroll
            for (int j = 0; j < 4; j++) {
                float p = __expf(s4[i][j] * SCALE - mnew);
                Ps[(tm + i) * PS_S + 4 * tc + j] = p;
                psum += p;
            }
#pragma unroll
            for (int msk_ = 1; msk_ < 16; msk_ <<= 1)
                psum += __shfl_xor_sync(0xffffffffu, psum, msk_);
            srow[i] = srow[i] * fac + psum;
#pragma unroll
            for (int j = 0; j < 8; j++) o[i][j] *= fac;
        }
        __syncthreads();   // Ps visible

        // O += P V  (rows tm+i, cols 4tc and 64+4tc)
#pragma unroll 4
        for (int k = 0; k < 64; k += 4) {
            float pv[4][4], vv[4][8];
#pragma unroll
            for (int i = 0; i < 4; i++)
                *(float4*)pv[i] = *(const float4*)&Ps[(tm + i) * PS_S + k];
#pragma unroll
            for (int kk = 0; kk < 4; kk++) {
                *(float4*)&vv[kk][0] = *(const float4*)&Vs[(k + kk) * 128 + 4 * tc];
                *(float4*)&vv[kk][4] = *(const float4*)&Vs[(k + kk) * 128 + 64 + 4 * tc];
            }
#pragma unroll
            for (int kk = 0; kk < 4; kk++)
#pragma unroll
                for (int i = 0; i < 4; i++)
#pragma unroll
                    for (int j = 0; j < 8; j++)
                        o[i][j] += pv[i][kk] * vv[kk][j];
        }
    }

    // epilogue: normalize and scatter ctx -> [B, L, HID]
    const int b = bh >> 5;
    const int h = bh & 31;
#pragma unroll
    for (int i = 0; i < 4; i++) {
        float inv = 1.0f / srow[i];
        size_t roff = (size_t)(b * LL + m0 + tm + i) * HID + h * HD;
#pragma unroll
        for (int j = 0; j < 4; j++) {
            g_ctx[roff + 4 * tc + j]      = o[i][j] * inv;
            g_ctx[roff + 64 + 4 * tc + j] = o[i][4 + j] * inv;
        }
    }
}

// -------- routed dense GEMM --------
__global__ void dense_gemm(float* __restrict__ out,
                           const float* __restrict__ Wv,
                           const float* __restrict__ Wl) {
    __shared__ float As[16][65];
    __shared__ __align__(16) float Bv[16][64];
    __shared__ __align__(16) float Bl[16][64];
    const int n0 = blockIdx.x * 64;
    const int m0 = blockIdx.y * 64;
    const int t  = threadIdx.x;
    const int tn = (t & 15) * 4;
    const int tm = (t >> 4) * 4;
    const int lm = t >> 2;
    const int lk = (t & 3) * 4;

    bool msk[4];
#pragma unroll
    for (int i = 0; i < 4; i++) msk[i] = (g_vm[m0 + tm + i] != 0);

    float acc[4][4] = {};
    for (int k0 = 0; k0 < HID; k0 += 16) {
        float4 a4 = *(const float4*)(g_ctx + (size_t)(m0 + lm) * HID + k0 + lk);
        float4 v4 = *(const float4*)(Wv + (size_t)(n0 + lm) * HID + k0 + lk);
        float4 l4 = *(const float4*)(Wl + (size_t)(n0 + lm) * HID + k0 + lk);
        As[lk+0][lm] = a4.x; As[lk+1][lm] = a4.y; As[lk+2][lm] = a4.z; As[lk+3][lm] = a4.w;
        Bv[lk+0][lm] = v4.x; Bv[lk+1][lm] = v4.y; Bv[lk+2][lm] = v4.z; Bv[lk+3][lm] = v4.w;
        Bl[lk+0][lm] = l4.x; Bl[lk+1][lm] = l4.y; Bl[lk+2][lm] = l4.z; Bl[lk+3][lm] = l4.w;
        __syncthreads();
#pragma unroll
        for (int k = 0; k < 16; k++) {
            float a[4];
#pragma unroll
            for (int i = 0; i < 4; i++) a[i] = As[k][tm + i];
            float4 wv = *(const float4*)&Bv[k][tn];
            float4 wl = *(const float4*)&Bl[k][tn];
#pragma unroll
            for (int i = 0; i < 4; i++) {
                float w0 = msk[i] ? wv.x : wl.x;
                float w1 = msk[i] ? wv.y : wl.y;
                float w2 = msk[i] ? wv.z : wl.z;
                float w3 = msk[i] ? wv.w : wl.w;
                acc[i][0] += a[i] * w0;
                acc[i][1] += a[i] * w1;
                acc[i][2] += a[i] * w2;
                acc[i][3] += a[i] * w3;
            }
        }
        __syncthreads();
    }
#pragma unroll
    for (int i = 0; i < 4; i++) {
        size_t roff = (size_t)(m0 + tm + i) * HID;
#pragma unroll
        for (int j = 0; j < 4; j++)
            out[roff + n0 + tn + j] = acc[i][j];
    }
}

extern "C" void kernel_launch(void* const* d_in, const int* in_sizes, int n_in,
                              void* d_out, int out_size) {
    const float* hs   = (const float*)d_in[0];
    const int*   tt   = (const int*)d_in[1];
    const int*   pos  = (const int*)d_in[2];
    // d_in[3] = attention_mask (all zeros; reference math ignores it)
    const float* wvq  = (const float*)d_in[4];
    const float* wlq  = (const float*)d_in[5];
    const float* wvd  = (const float*)d_in[6];
    const float* wld  = (const float*)d_in[7];
    float* out = (float*)d_out;

    cudaFuncSetAttribute(flash_attn, cudaFuncAttributeMaxDynamicSharedMemorySize,
                         SM_TOT * (int)sizeof(float));

    prep_kernel<<<1024, 256>>>(tt);
    qkv_gemm<<<dim3(QKVN / 64, MM / 64), 256>>>(hs, wvq, wlq);
    rope_kernel<<<BH * LL, 128>>>(pos);
    flash_attn<<<dim3(LL / 64, BH), 256, SM_TOT * (int)sizeof(float)>>>();
    dense_gemm<<<dim3(HID / 64, MM / 64), 256>>>(out, wvd, wld);
}

// round 4
// speedup vs baseline: 3.6694x; 3.6694x over previous
#include <cuda_runtime.h>
#include <math.h>

#define BB 2
#define LL 2048
#define HID 4096
#define NH 32
#define HD 128
#define MM (BB*LL)           // 4096 tokens
#define QKVN (3*HID)         // 12288
#define BH (BB*NH)           // 64
#define SCALE 0.08838834764831845f   // 1/sqrt(128)
#define PADM 4224            // 33 * 128 row slots (padded partition)
#define MBLK 33

// -------- scratch (static device globals; allocation-free) --------
__device__ float g_q[(size_t)BH*LL*HD];        // [B,NH,L,D] 64MB
__device__ float g_k[(size_t)BH*LL*HD];        // 64MB
__device__ float g_v[(size_t)BH*LL*HD];        // 64MB
__device__ float g_ctx[(size_t)PADM*HID];      // permuted ctx rows
__device__ int   g_vm[MM];
__device__ int   g_perm[PADM];                 // permuted row -> token (-1 = pad)
__device__ int   g_iperm[MM];                  // token -> permuted row
__device__ int   g_NvPad;
__device__ float g_cos[LL*HD];
__device__ float g_sin[LL*HD];

// -------- prep: vision mask + RoPE tables --------
__global__ void prep_kernel(const int* __restrict__ tt) {
    int idx = blockIdx.x * blockDim.x + threadIdx.x;
    if (idx < MM) {
        int l = idx & (LL - 1);
        g_vm[idx] = (l < LL - 1) && (tt[idx] == 1) && (tt[idx + 1] == 1);
    }
    if (idx < LL * HD) {
        int p = idx / HD;
        int d = idx & (HD - 1);
        int j = d & 63;
        double inv = exp(-log(10000.0) * (double)(2 * j) / 128.0);
        double ang = (double)p * inv;
        g_cos[idx] = (float)cos(ang);
        g_sin[idx] = (float)sin(ang);
    }
}

// -------- deterministic partition scan (1 block) --------
__global__ void scan_kernel() {
    __shared__ int s[1024];
    int t = threadIdx.x;
    int flags[4];
    int c = 0;
#pragma unroll
    for (int i = 0; i < 4; i++) { flags[i] = g_vm[t * 4 + i]; c += flags[i]; }
    s[t] = c;
    __syncthreads();
    for (int off = 1; off < 1024; off <<= 1) {
        int v = s[t];
        int add = (t >= off) ? s[t - off] : 0;
        __syncthreads();
        s[t] = v + add;
        __syncthreads();
    }
    int Nv = s[1023];
    int ex = s[t] - c;           // exclusive prefix of vision count
    int nvpad = (Nv + 127) & ~127;
    for (int i = t; i < PADM; i += 1024) g_perm[i] = -1;
    __syncthreads();
    int vrun = ex;
#pragma unroll
    for (int i = 0; i < 4; i++) {
        int g = t * 4 + i;
        int dst;
        if (flags[i]) { dst = vrun; vrun++; }
        else          { dst = nvpad + (g - vrun); }
        g_perm[dst] = g;
        g_iperm[g] = dst;
    }
    if (t == 0) g_NvPad = nvpad;
}

// -------- TF32 helpers --------
__device__ __forceinline__ unsigned f2tf32(float f) {
    unsigned o;
    asm("cvt.rna.tf32.f32 %0, %1;" : "=r"(o) : "f"(f));
    return o;
}
__device__ __forceinline__ void mma_tf32(float* d, const unsigned* a, const unsigned* b) {
    asm volatile(
        "mma.sync.aligned.m16n8k8.row.col.f32.tf32.tf32.f32 "
        "{%0,%1,%2,%3},{%4,%5,%6,%7},{%8,%9},{%0,%1,%2,%3};\n"
        : "+f"(d[0]), "+f"(d[1]), "+f"(d[2]), "+f"(d[3])
        : "r"(a[0]), "r"(a[1]), "r"(a[2]), "r"(a[3]), "r"(b[0]), "r"(b[1]));
}

#define KS 36   // smem k-stride (32 + 4 pad -> conflict-free quads)

// -------- routed QKV GEMM on tensor cores (TF32) --------
// C[m,n] = hs[perm[m],:] . Wsel[n,:],  W chosen per 128-row block by partition
__global__ __launch_bounds__(256) void qkv_mma(const float* __restrict__ A,
                                               const float* __restrict__ Wv,
                                               const float* __restrict__ Wl) {
    __shared__ unsigned As[128][KS];
    __shared__ unsigned Bs[128][KS];
    const int m0 = blockIdx.x * 128;
    const int n0 = blockIdx.y * 128;
    const int t = threadIdx.x;
    const int lane = t & 31, w = t >> 5;
    const int wm = (w & 1) * 64, wn = (w >> 1) * 32;
    const int lr = t >> 1;              // load row 0..127
    const int lk = (t & 1) * 16;        // k offset 0/16
    const int qr = lane >> 2, qc = lane & 3;

    const float* W = (m0 < g_NvPad) ? Wv : Wl;
    int tokA = g_perm[m0 + lr];
    const float* Arow = A + (size_t)(tokA < 0 ? 0 : tokA) * HID + lk;
    const float* Brow = W + (size_t)(n0 + lr) * HID + lk;

    float acc[4][4][4] = {};
    for (int k0 = 0; k0 < HID; k0 += 32) {
        float4 av[4], bv[4];
#pragma unroll
        for (int i = 0; i < 4; i++) {
            av[i] = *(const float4*)(Arow + k0 + 4 * i);
            bv[i] = *(const float4*)(Brow + k0 + 4 * i);
        }
        __syncthreads();
#pragma unroll
        for (int i = 0; i < 4; i++) {
            *(uint4*)&As[lr][lk + 4 * i] = make_uint4(f2tf32(av[i].x), f2tf32(av[i].y), f2tf32(av[i].z), f2tf32(av[i].w));
            *(uint4*)&Bs[lr][lk + 4 * i] = make_uint4(f2tf32(bv[i].x), f2tf32(bv[i].y), f2tf32(bv[i].z), f2tf32(bv[i].w));
        }
        __syncthreads();
#pragma unroll
        for (int kc = 0; kc < 32; kc += 8) {
            unsigned bf[4][2];
#pragma unroll
            for (int nt = 0; nt < 4; nt++) {
                bf[nt][0] = Bs[wn + nt * 8 + qr][kc + qc];
                bf[nt][1] = Bs[wn + nt * 8 + qr][kc + qc + 4];
            }
#pragma unroll
            for (int mt = 0; mt < 4; mt++) {
                unsigned af[4];
                af[0] = As[wm + mt * 16 + qr][kc + qc];
                af[1] = As[wm + mt * 16 + qr + 8][kc + qc];
                af[2] = As[wm + mt * 16 + qr][kc + qc + 4];
                af[3] = As[wm + mt * 16 + qr + 8][kc + qc + 4];
#pragma unroll
                for (int nt = 0; nt < 4; nt++)
                    mma_tf32(acc[mt][nt], af, bf[nt]);
            }
        }
    }
    // epilogue: scatter q/k/v at original token rows
#pragma unroll
    for (int mt = 0; mt < 4; mt++) {
        int r0 = m0 + wm + mt * 16 + qr;
        int tok0 = g_perm[r0], tok1 = g_perm[r0 + 8];
#pragma unroll
        for (int nt = 0; nt < 4; nt++) {
            int cb = n0 + wn + nt * 8 + qc * 2;
            int part = cb >> 12, rem = cb & 4095, head = rem >> 7, dd = rem & 127;
            float* base = (part == 0) ? g_q : (part == 1) ? g_k : g_v;
            if (tok0 >= 0) {
                int b = tok0 >> 11, l = tok0 & 2047;
                *(float2*)&base[((size_t)(b * NH + head) * LL + l) * HD + dd] =
                    make_float2(acc[mt][nt][0], acc[mt][nt][1]);
            }
            if (tok1 >= 0) {
                int b = tok1 >> 11, l = tok1 & 2047;
                *(float2*)&base[((size_t)(b * NH + head) * LL + l) * HD + dd] =
                    make_float2(acc[mt][nt][2], acc[mt][nt][3]);
            }
        }
    }
}

// -------- routed dense GEMM on tensor cores (TF32), A = permuted ctx --------
__global__ __launch_bounds__(256) void dense_mma(float* __restrict__ out,
                                                 const float* __restrict__ Wv,
                                                 const float* __restrict__ Wl) {
    __shared__ unsigned As[128][KS];
    __shared__ unsigned Bs[128][KS];
    const int m0 = blockIdx.x * 128;
    const int n0 = blockIdx.y * 128;
    const int t = threadIdx.x;
    const int lane = t & 31, w = t >> 5;
    const int wm = (w & 1) * 64, wn = (w >> 1) * 32;
    const int lr = t >> 1;
    const int lk = (t & 1) * 16;
    const int qr = lane >> 2, qc = lane & 3;

    const float* W = (m0 < g_NvPad) ? Wv : Wl;
    const float* Arow = g_ctx + (size_t)(m0 + lr) * HID + lk;
    const float* Brow = W + (size_t)(n0 + lr) * HID + lk;

    float acc[4][4][4] = {};
    for (int k0 = 0; k0 < HID; k0 += 32) {
        float4 av[4], bv[4];
#pragma unroll
        for (int i = 0; i < 4; i++) {
            av[i] = *(const float4*)(Arow + k0 + 4 * i);
            bv[i] = *(const float4*)(Brow + k0 + 4 * i);
        }
        __syncthreads();
#pragma unroll
        for (int i = 0; i < 4; i++) {
            *(uint4*)&As[lr][lk + 4 * i] = make_uint4(f2tf32(av[i].x), f2tf32(av[i].y), f2tf32(av[i].z), f2tf32(av[i].w));
            *(uint4*)&Bs[lr][lk + 4 * i] = make_uint4(f2tf32(bv[i].x), f2tf32(bv[i].y), f2tf32(bv[i].z), f2tf32(bv[i].w));
        }
        __syncthreads();
#pragma unroll
        for (int kc = 0; kc < 32; kc += 8) {
            unsigned bf[4][2];
#pragma unroll
            for (int nt = 0; nt < 4; nt++) {
                bf[nt][0] = Bs[wn + nt * 8 + qr][kc + qc];
                bf[nt][1] = Bs[wn + nt * 8 + qr][kc + qc + 4];
            }
#pragma unroll
            for (int mt = 0; mt < 4; mt++) {
                unsigned af[4];
                af[0] = As[wm + mt * 16 + qr][kc + qc];
                af[1] = As[wm + mt * 16 + qr + 8][kc + qc];
                af[2] = As[wm + mt * 16 + qr][kc + qc + 4];
                af[3] = As[wm + mt * 16 + qr + 8][kc + qc + 4];
#pragma unroll
                for (int nt = 0; nt < 4; nt++)
                    mma_tf32(acc[mt][nt], af, bf[nt]);
            }
        }
    }
#pragma unroll
    for (int mt = 0; mt < 4; mt++) {
        int r0 = m0 + wm + mt * 16 + qr;
        int tok0 = g_perm[r0], tok1 = g_perm[r0 + 8];
#pragma unroll
        for (int nt = 0; nt < 4; nt++) {
            int cb = n0 + wn + nt * 8 + qc * 2;
            if (tok0 >= 0)
                *(float2*)&out[(size_t)tok0 * HID + cb] = make_float2(acc[mt][nt][0], acc[mt][nt][1]);
            if (tok1 >= 0)
                *(float2*)&out[(size_t)tok1 * HID + cb] = make_float2(acc[mt][nt][2], acc[mt][nt][3]);
        }
    }
}

// -------- RoPE in-place on g_q, g_k --------
__global__ void rope_kernel(const int* __restrict__ pos_ids) {
    int blk = blockIdx.x;
    int l  = blk & (LL - 1);
    int bh = blk >> 11;
    int b  = bh >> 5;
    int d  = threadIdx.x;
    int p  = pos_ids[b * LL + l];
    if (p < 0) p = 0;
    if (p >= LL) p = LL - 1;
    size_t base = ((size_t)bh * LL + l) * HD;
    float c = g_cos[p * HD + d];
    float s = g_sin[p * HD + d];
    int pd = (d < 64) ? d + 64 : d - 64;
    float q0 = g_q[base + d], qp = g_q[base + pd];
    float k0 = g_k[base + d], kp = g_k[base + pd];
    float qr = (d < 64) ? -qp : qp;
    float kr = (d < 64) ? -kp : kp;
    __syncthreads();
    g_q[base + d] = q0 * c + qr * s;
    g_k[base + d] = k0 * c + kr * s;
}

// -------- fused flash attention (fp32, online softmax) --------
#define KT_S 68
#define PS_S 68
#define SM_QS 0
#define SM_KT (64*128)
#define SM_VS (SM_KT + 128*KT_S)
#define SM_PS (SM_VS + 64*128)
#define SM_TOT (SM_PS + 64*PS_S)

__global__ void flash_attn() {
    extern __shared__ float sm[];
    float* Qs = sm + SM_QS;
    float* Kt = sm + SM_KT;
    float* Vs = sm + SM_VS;
    float* Ps = sm + SM_PS;

    const int bh = blockIdx.y;
    const int m0 = blockIdx.x * 64;
    const float* Q = g_q + (size_t)bh * LL * HD;
    const float* K = g_k + (size_t)bh * LL * HD;
    const float* V = g_v + (size_t)bh * LL * HD;

    const int t = threadIdx.x;
    const int row_l = t >> 2;
    const int kb4   = (t & 3) * 4;
    const int tm = (t >> 4) * 4;
    const int tc = t & 15;

#pragma unroll
    for (int it = 0; it < 8; it++) {
        int k = kb4 + it * 16;
        *(float4*)&Qs[row_l * 128 + k] = *(const float4*)&Q[(size_t)(m0 + row_l) * HD + k];
    }

    float o[4][8];
    float mrow[4], srow[4];
#pragma unroll
    for (int i = 0; i < 4; i++) {
        mrow[i] = -1e30f; srow[i] = 0.f;
#pragma unroll
        for (int j = 0; j < 8; j++) o[i][j] = 0.f;
    }

    for (int j0 = 0; j0 < LL; j0 += 64) {
        __syncthreads();
#pragma unroll
        for (int it = 0; it < 8; it++) {
            int k = kb4 + it * 16;
            float4 kv = *(const float4*)&K[(size_t)(j0 + row_l) * HD + k];
            Kt[(k + 0) * KT_S + row_l] = kv.x;
            Kt[(k + 1) * KT_S + row_l] = kv.y;
            Kt[(k + 2) * KT_S + row_l] = kv.z;
            Kt[(k + 3) * KT_S + row_l] = kv.w;
            *(float4*)&Vs[row_l * 128 + k] = *(const float4*)&V[(size_t)(j0 + row_l) * HD + k];
        }
        __syncthreads();

        float s4[4][4] = {};
#pragma unroll 8
        for (int k = 0; k < 128; k += 4) {
            float qv[4][4], kv[4][4];
#pragma unroll
            for (int i = 0; i < 4; i++)
                *(float4*)qv[i] = *(const float4*)&Qs[(tm + i) * 128 + k];
#pragma unroll
            for (int kk = 0; kk < 4; kk++)
                *(float4*)kv[kk] = *(const float4*)&Kt[(k + kk) * KT_S + 4 * tc];
#pragma unroll
            for (int kk = 0; kk < 4; kk++)
#pragma unroll
                for (int i = 0; i < 4; i++)
#pragma unroll
                    for (int j = 0; j < 4; j++)
                        s4[i][j] += qv[i][kk] * kv[kk][j];
        }

#pragma unroll
        for (int i = 0; i < 4; i++) {
            float tmax = s4[i][0];
#pragma unroll
            for (int j = 1; j < 4; j++) tmax = fmaxf(tmax, s4[i][j]);
#pragma unroll
            for (int msk_ = 1; msk_ < 16; msk_ <<= 1)
                tmax = fmaxf(tmax, __shfl_xor_sync(0xffffffffu, tmax, msk_));
            tmax *= SCALE;
            float mnew = fmaxf(mrow[i], tmax);
            float fac  = __expf(mrow[i] - mnew);
            mrow[i] = mnew;
            float psum = 0.f;
#pragma unroll
            for (int j = 0; j < 4; j++) {
                float p = __expf(s4[i][j] * SCALE - mnew);
                Ps[(tm + i) * PS_S + 4 * tc + j] = p;
                psum += p;
            }
#pragma unroll
            for (int msk_ = 1; msk_ < 16; msk_ <<= 1)
                psum += __shfl_xor_sync(0xffffffffu, psum, msk_);
            srow[i] = srow[i] * fac + psum;
#pragma unroll
            for (int j = 0; j < 8; j++) o[i][j] *= fac;
        }
        __syncthreads();

#pragma unroll 4
        for (int k = 0; k < 64; k += 4) {
            float pv[4][4], vv[4][8];
#pragma unroll
            for (int i = 0; i < 4; i++)
                *(float4*)pv[i] = *(const float4*)&Ps[(tm + i) * PS_S + k];
#pragma unroll
            for (int kk = 0; kk < 4; kk++) {
                *(float4*)&vv[kk][0] = *(const float4*)&Vs[(k + kk) * 128 + 4 * tc];
                *(float4*)&vv[kk][4] = *(const float4*)&Vs[(k + kk) * 128 + 64 + 4 * tc];
            }
#pragma unroll
            for (int kk = 0; kk < 4; kk++)
#pragma unroll
                for (int i = 0; i < 4; i++)
#pragma unroll
                    for (int j = 0; j < 8; j++)
                        o[i][j] += pv[i][kk] * vv[kk][j];
        }
    }

    // epilogue: normalize, write ctx in PERMUTED row order for dense GEMM
    const int b = bh >> 5;
    const int h = bh & 31;
#pragma unroll
    for (int i = 0; i < 4; i++) {
        float inv = 1.0f / srow[i];
        int tok = b * LL + m0 + tm + i;
        int prow = g_iperm[tok];
        size_t roff = (size_t)prow * HID + h * HD;
#pragma unroll
        for (int j = 0; j < 4; j++) {
            g_ctx[roff + 4 * tc + j]      = o[i][j] * inv;
            g_ctx[roff + 64 + 4 * tc + j] = o[i][4 + j] * inv;
        }
    }
}

extern "C" void kernel_launch(void* const* d_in, const int* in_sizes, int n_in,
                              void* d_out, int out_size) {
    const float* hs   = (const float*)d_in[0];
    const int*   tt   = (const int*)d_in[1];
    const int*   pos  = (const int*)d_in[2];
    // d_in[3] = attention_mask (all zeros; reference math ignores it)
    const float* wvq  = (const float*)d_in[4];
    const float* wlq  = (const float*)d_in[5];
    const float* wvd  = (const float*)d_in[6];
    const float* wld  = (const float*)d_in[7];
    float* out = (float*)d_out;

    cudaFuncSetAttribute(flash_attn, cudaFuncAttributeMaxDynamicSharedMemorySize,
                         SM_TOT * (int)sizeof(float));

    prep_kernel<<<1024, 256>>>(tt);
    scan_kernel<<<1, 1024>>>();
    qkv_mma<<<dim3(MBLK, QKVN / 128), 256>>>(hs, wvq, wlq);
    rope_kernel<<<BH * LL, 128>>>(pos);
    flash_attn<<<dim3(LL / 64, BH), 256, SM_TOT * (int)sizeof(float)>>>();
    dense_mma<<<dim3(MBLK, HID / 128), 256>>>(out, wvd, wld);
}

// round 8
// speedup vs baseline: 5.1887x; 1.4141x over previous
#include <cuda_runtime.h>
#include <math.h>

#define BB 2
#define LL 2048
#define HID 4096
#define NH 32
#define HD 128
#define MM (BB*LL)           // 4096 tokens
#define QKVN (3*HID)         // 12288
#define BH (BB*NH)           // 64
#define SCALE 0.08838834764831845f   // 1/sqrt(128)
#define C2E 0.1275313945069287f      // SCALE * log2(e)
#define PADM 4224
#define MBLK 33

// -------- scratch (static device globals; allocation-free) --------
__device__ float g_q[(size_t)BH*LL*HD];
__device__ float g_k[(size_t)BH*LL*HD];
__device__ float g_v[(size_t)BH*LL*HD];
__device__ float g_ctx[(size_t)PADM*HID];
__device__ int   g_vm[MM];
__device__ int   g_perm[PADM];
__device__ int   g_iperm[MM];
__device__ int   g_NvPad;
__device__ float g_cos[LL*HD];
__device__ float g_sin[LL*HD];

// -------- prep --------
__global__ void prep_kernel(const int* __restrict__ tt) {
    int idx = blockIdx.x * blockDim.x + threadIdx.x;
    if (idx < MM) {
        int l = idx & (LL - 1);
        g_vm[idx] = (l < LL - 1) && (tt[idx] == 1) && (tt[idx + 1] == 1);
    }
    if (idx < LL * HD) {
        int p = idx / HD;
        int d = idx & (HD - 1);
        int j = d & 63;
        double inv = exp(-log(10000.0) * (double)(2 * j) / 128.0);
        double ang = (double)p * inv;
        g_cos[idx] = (float)cos(ang);
        g_sin[idx] = (float)sin(ang);
    }
}

// -------- deterministic partition scan --------
__global__ void scan_kernel() {
    __shared__ int s[1024];
    int t = threadIdx.x;
    int flags[4];
    int c = 0;
#pragma unroll
    for (int i = 0; i < 4; i++) { flags[i] = g_vm[t * 4 + i]; c += flags[i]; }
    s[t] = c;
    __syncthreads();
    for (int off = 1; off < 1024; off <<= 1) {
        int v = s[t];
        int add = (t >= off) ? s[t - off] : 0;
        __syncthreads();
        s[t] = v + add;
        __syncthreads();
    }
    int Nv = s[1023];
    int ex = s[t] - c;
    int nvpad = (Nv + 127) & ~127;
    for (int i = t; i < PADM; i += 1024) g_perm[i] = -1;
    __syncthreads();
    int vrun = ex;
#pragma unroll
    for (int i = 0; i < 4; i++) {
        int g = t * 4 + i;
        int dst;
        if (flags[i]) { dst = vrun; vrun++; }
        else          { dst = nvpad + (g - vrun); }
        g_perm[dst] = g;
        g_iperm[g] = dst;
    }
    if (t == 0) g_NvPad = nvpad;
}

// -------- TF32 helpers --------
__device__ __forceinline__ unsigned f2tf32(float f) {
    unsigned o;
    asm("cvt.rna.tf32.f32 %0, %1;" : "=r"(o) : "f"(f));
    return o;
}
__device__ __forceinline__ float fexp2(float x) {
    float y;
    asm("ex2.approx.ftz.f32 %0, %1;" : "=f"(y) : "f"(x));
    return y;
}
__device__ __forceinline__ void mma_tf32(float* d, const unsigned* a, const unsigned* b) {
    asm volatile(
        "mma.sync.aligned.m16n8k8.row.col.f32.tf32.tf32.f32 "
        "{%0,%1,%2,%3},{%4,%5,%6,%7},{%8,%9},{%0,%1,%2,%3};\n"
        : "+f"(d[0]), "+f"(d[1]), "+f"(d[2]), "+f"(d[3])
        : "r"(a[0]), "r"(a[1]), "r"(a[2]), "r"(a[3]), "r"(b[0]), "r"(b[1]));
}

#define KS 36

// -------- routed QKV GEMM (TF32 MMA) --------
__global__ __launch_bounds__(256) void qkv_mma(const float* __restrict__ A,
                                               const float* __restrict__ Wv,
                                               const float* __restrict__ Wl) {
    __shared__ unsigned As[128][KS];
    __shared__ unsigned Bs[128][KS];
    const int m0 = blockIdx.x * 128;
    const int n0 = blockIdx.y * 128;
    const int t = threadIdx.x;
    const int lane = t & 31, w = t >> 5;
    const int wm = (w & 1) * 64, wn = (w >> 1) * 32;
    const int lr = t >> 1;
    const int lk = (t & 1) * 16;
    const int qr = lane >> 2, qc = lane & 3;

    const float* W = (m0 < g_NvPad) ? Wv : Wl;
    int tokA = g_perm[m0 + lr];
    const float* Arow = A + (size_t)(tokA < 0 ? 0 : tokA) * HID + lk;
    const float* Brow = W + (size_t)(n0 + lr) * HID + lk;

    float acc[4][4][4] = {};
    for (int k0 = 0; k0 < HID; k0 += 32) {
        float4 av[4], bv[4];
#pragma unroll
        for (int i = 0; i < 4; i++) {
            av[i] = *(const float4*)(Arow + k0 + 4 * i);
            bv[i] = *(const float4*)(Brow + k0 + 4 * i);
        }
        __syncthreads();
#pragma unroll
        for (int i = 0; i < 4; i++) {
            *(uint4*)&As[lr][lk + 4 * i] = make_uint4(f2tf32(av[i].x), f2tf32(av[i].y), f2tf32(av[i].z), f2tf32(av[i].w));
            *(uint4*)&Bs[lr][lk + 4 * i] = make_uint4(f2tf32(bv[i].x), f2tf32(bv[i].y), f2tf32(bv[i].z), f2tf32(bv[i].w));
        }
        __syncthreads();
#pragma unroll
        for (int kc = 0; kc < 32; kc += 8) {
            unsigned bf[4][2];
#pragma unroll
            for (int nt = 0; nt < 4; nt++) {
                bf[nt][0] = Bs[wn + nt * 8 + qr][kc + qc];
                bf[nt][1] = Bs[wn + nt * 8 + qr][kc + qc + 4];
            }
#pragma unroll
            for (int mt = 0; mt < 4; mt++) {
                unsigned af[4];
                af[0] = As[wm + mt * 16 + qr][kc + qc];
                af[1] = As[wm + mt * 16 + qr + 8][kc + qc];
                af[2] = As[wm + mt * 16 + qr][kc + qc + 4];
                af[3] = As[wm + mt * 16 + qr + 8][kc + qc + 4];
#pragma unroll
                for (int nt = 0; nt < 4; nt++)
                    mma_tf32(acc[mt][nt], af, bf[nt]);
            }
        }
    }
#pragma unroll
    for (int mt = 0; mt < 4; mt++) {
        int r0 = m0 + wm + mt * 16 + qr;
        int tok0 = g_perm[r0], tok1 = g_perm[r0 + 8];
#pragma unroll
        for (int nt = 0; nt < 4; nt++) {
            int cb = n0 + wn + nt * 8 + qc * 2;
            int part = cb >> 12, rem = cb & 4095, head = rem >> 7, dd = rem & 127;
            float* base = (part == 0) ? g_q : (part == 1) ? g_k : g_v;
            if (tok0 >= 0) {
                int b = tok0 >> 11, l = tok0 & 2047;
                *(float2*)&base[((size_t)(b * NH + head) * LL + l) * HD + dd] =
                    make_float2(acc[mt][nt][0], acc[mt][nt][1]);
            }
            if (tok1 >= 0) {
                int b = tok1 >> 11, l = tok1 & 2047;
                *(float2*)&base[((size_t)(b * NH + head) * LL + l) * HD + dd] =
                    make_float2(acc[mt][nt][2], acc[mt][nt][3]);
            }
        }
    }
}

// -------- routed dense GEMM (TF32 MMA) --------
__global__ __launch_bounds__(256) void dense_mma(float* __restrict__ out,
                                                 const float* __restrict__ Wv,
                                                 const float* __restrict__ Wl) {
    __shared__ unsigned As[128][KS];
    __shared__ unsigned Bs[128][KS];
    const int m0 = blockIdx.x * 128;
    const int n0 = blockIdx.y * 128;
    const int t = threadIdx.x;
    const int lane = t & 31, w = t >> 5;
    const int wm = (w & 1) * 64, wn = (w >> 1) * 32;
    const int lr = t >> 1;
    const int lk = (t & 1) * 16;
    const int qr = lane >> 2, qc = lane & 3;

    const float* W = (m0 < g_NvPad) ? Wv : Wl;
    const float* Arow = g_ctx + (size_t)(m0 + lr) * HID + lk;
    const float* Brow = W + (size_t)(n0 + lr) * HID + lk;

    float acc[4][4][4] = {};
    for (int k0 = 0; k0 < HID; k0 += 32) {
        float4 av[4], bv[4];
#pragma unroll
        for (int i = 0; i < 4; i++) {
            av[i] = *(const float4*)(Arow + k0 + 4 * i);
            bv[i] = *(const float4*)(Brow + k0 + 4 * i);
        }
        __syncthreads();
#pragma unroll
        for (int i = 0; i < 4; i++) {
            *(uint4*)&As[lr][lk + 4 * i] = make_uint4(f2tf32(av[i].x), f2tf32(av[i].y), f2tf32(av[i].z), f2tf32(av[i].w));
            *(uint4*)&Bs[lr][lk + 4 * i] = make_uint4(f2tf32(bv[i].x), f2tf32(bv[i].y), f2tf32(bv[i].z), f2tf32(bv[i].w));
        }
        __syncthreads();
#pragma unroll
        for (int kc = 0; kc < 32; kc += 8) {
            unsigned bf[4][2];
#pragma unroll
            for (int nt = 0; nt < 4; nt++) {
                bf[nt][0] = Bs[wn + nt * 8 + qr][kc + qc];
                bf[nt][1] = Bs[wn + nt * 8 + qr][kc + qc + 4];
            }
#pragma unroll
            for (int mt = 0; mt < 4; mt++) {
                unsigned af[4];
                af[0] = As[wm + mt * 16 + qr][kc + qc];
                af[1] = As[wm + mt * 16 + qr + 8][kc + qc];
                af[2] = As[wm + mt * 16 + qr][kc + qc + 4];
                af[3] = As[wm + mt * 16 + qr + 8][kc + qc + 4];
#pragma unroll
                for (int nt = 0; nt < 4; nt++)
                    mma_tf32(acc[mt][nt], af, bf[nt]);
            }
        }
    }
#pragma unroll
    for (int mt = 0; mt < 4; mt++) {
        int r0 = m0 + wm + mt * 16 + qr;
        int tok0 = g_perm[r0], tok1 = g_perm[r0 + 8];
#pragma unroll
        for (int nt = 0; nt < 4; nt++) {
            int cb = n0 + wn + nt * 8 + qc * 2;
            if (tok0 >= 0)
                *(float2*)&out[(size_t)tok0 * HID + cb] = make_float2(acc[mt][nt][0], acc[mt][nt][1]);
            if (tok1 >= 0)
                *(float2*)&out[(size_t)tok1 * HID + cb] = make_float2(acc[mt][nt][2], acc[mt][nt][3]);
        }
    }
}

// -------- RoPE in-place --------
__global__ void rope_kernel(const int* __restrict__ pos_ids) {
    int blk = blockIdx.x;
    int l  = blk & (LL - 1);
    int bh = blk >> 11;
    int b  = bh >> 5;
    int d  = threadIdx.x;
    int p  = pos_ids[b * LL + l];
    if (p < 0) p = 0;
    if (p >= LL) p = LL - 1;
    size_t base = ((size_t)bh * LL + l) * HD;
    float c = g_cos[p * HD + d];
    float s = g_sin[p * HD + d];
    int pd = (d < 64) ? d + 64 : d - 64;
    float q0 = g_q[base + d], qp = g_q[base + pd];
    float k0 = g_k[base + d], kp = g_k[base + pd];
    float qr = (d < 64) ? -qp : qp;
    float kr = (d < 64) ? -kp : kp;
    __syncthreads();
    g_q[base + d] = q0 * c + qr * s;
    g_k[base + d] = k0 * c + kr * s;
}

// -------- flash attention on tensor cores (TF32) --------
// block: 256 thr (8 warps), q-tile 128 rows (warp = 16 rows), kv-tile 64.
#define QS_S 132
#define KS_S 132
#define VT_S 68
#define FPS_S 68
#define SMF_QS 0
#define SMF_KS (128*QS_S)
#define SMF_VT (SMF_KS + 64*KS_S)
#define SMF_PS (SMF_VT + 128*VT_S)
#define SMF_TOT (SMF_PS + 128*FPS_S)   // 42752 words = 171008 bytes

__global__ __launch_bounds__(256) void flash_mma() {
    extern __shared__ unsigned smu[];
    unsigned* Qs = smu + SMF_QS;
    unsigned* Ks = smu + SMF_KS;
    unsigned* Vt = smu + SMF_VT;
    unsigned* Ps = smu + SMF_PS;

    const int bh = blockIdx.y;
    const int m0 = blockIdx.x * 128;
    const float* Q = g_q + (size_t)bh * LL * HD;
    const float* K = g_k + (size_t)bh * LL * HD;
    const float* V = g_v + (size_t)bh * LL * HD;

    const int t = threadIdx.x;
    const int lane = t & 31, w = t >> 5;
    const int wm = w * 16;
    const int qr = lane >> 2, qc = lane & 3;

    // --- load + convert Q tile (128x128) ---
    {
        const int lr = t >> 1;            // row 0..127
        const int lkh = (t & 1) * 64;     // half of the 128 dims
#pragma unroll
        for (int i = 0; i < 16; i++) {
            float4 q4 = *(const float4*)&Q[(size_t)(m0 + lr) * HD + lkh + 4 * i];
            *(uint4*)&Qs[lr * QS_S + lkh + 4 * i] =
                make_uint4(f2tf32(q4.x), f2tf32(q4.y), f2tf32(q4.z), f2tf32(q4.w));
        }
    }

    float o[16][4];
#pragma unroll
    for (int nt = 0; nt < 16; nt++)
#pragma unroll
        for (int j = 0; j < 4; j++) o[nt][j] = 0.f;
    float mrow0 = -1e30f, mrow1 = -1e30f, srow0 = 0.f, srow1 = 0.f;

    const int krow = t >> 2;              // 0..63
    const int kc4  = (t & 3) * 4;         // float4 col base, step 16

    for (int j0 = 0; j0 < LL; j0 += 64) {
        __syncthreads();   // prior iteration's reads of Ks/Vt complete
        // --- load + convert K, V tiles ---
#pragma unroll
        for (int i = 0; i < 8; i++) {
            int col = kc4 + 16 * i;
            float4 k4 = *(const float4*)&K[(size_t)(j0 + krow) * HD + col];
            *(uint4*)&Ks[krow * KS_S + col] =
                make_uint4(f2tf32(k4.x), f2tf32(k4.y), f2tf32(k4.z), f2tf32(k4.w));
            float4 v4 = *(const float4*)&V[(size_t)(j0 + krow) * HD + col];
            Vt[(col + 0) * VT_S + krow] = f2tf32(v4.x);
            Vt[(col + 1) * VT_S + krow] = f2tf32(v4.y);
            Vt[(col + 2) * VT_S + krow] = f2tf32(v4.z);
            Vt[(col + 3) * VT_S + krow] = f2tf32(v4.w);
        }
        __syncthreads();

        // --- S = Q K^T : warp computes 16 rows x 64 cols ---
        float accs[8][4];
#pragma unroll
        for (int nt = 0; nt < 8; nt++)
#pragma unroll
            for (int j = 0; j < 4; j++) accs[nt][j] = 0.f;
#pragma unroll
        for (int kc = 0; kc < 128; kc += 8) {
            unsigned af[4];
            af[0] = Qs[(wm + qr) * QS_S + kc + qc];
            af[1] = Qs[(wm + qr + 8) * QS_S + kc + qc];
            af[2] = Qs[(wm + qr) * QS_S + kc + qc + 4];
            af[3] = Qs[(wm + qr + 8) * QS_S + kc + qc + 4];
#pragma unroll
            for (int nt = 0; nt < 8; nt++) {
                unsigned bf[2];
                bf[0] = Ks[(nt * 8 + qr) * KS_S + kc + qc];
                bf[1] = Ks[(nt * 8 + qr) * KS_S + kc + qc + 4];
                mma_tf32(accs[nt], af, bf);
            }
        }

        // --- online softmax (warp-local, rows qr and qr+8) ---
        float tm0 = -1e30f, tm1 = -1e30f;
#pragma unroll
        for (int nt = 0; nt < 8; nt++) {
            tm0 = fmaxf(tm0, fmaxf(accs[nt][0], accs[nt][1]));
            tm1 = fmaxf(tm1, fmaxf(accs[nt][2], accs[nt][3]));
        }
        tm0 *= C2E; tm1 *= C2E;
#pragma unroll
        for (int ms = 1; ms < 4; ms <<= 1) {
            tm0 = fmaxf(tm0, __shfl_xor_sync(0xffffffffu, tm0, ms));
            tm1 = fmaxf(tm1, __shfl_xor_sync(0xffffffffu, tm1, ms));
        }
        float mn0 = fmaxf(mrow0, tm0), mn1 = fmaxf(mrow1, tm1);
        float fac0 = fexp2(mrow0 - mn0), fac1 = fexp2(mrow1 - mn1);
        mrow0 = mn0; mrow1 = mn1;
        float sum0 = 0.f, sum1 = 0.f;
#pragma unroll
        for (int nt = 0; nt < 8; nt++) {
            float p0 = fexp2(accs[nt][0] * C2E - mn0);
            float p1 = fexp2(accs[nt][1] * C2E - mn0);
            float p2 = fexp2(accs[nt][2] * C2E - mn1);
            float p3 = fexp2(accs[nt][3] * C2E - mn1);
            sum0 += p0 + p1; sum1 += p2 + p3;
            *(uint2*)&Ps[(wm + qr) * FPS_S + nt * 8 + 2 * qc] =
                make_uint2(f2tf32(p0), f2tf32(p1));
            *(uint2*)&Ps[(wm + qr + 8) * FPS_S + nt * 8 + 2 * qc] =
                make_uint2(f2tf32(p2), f2tf32(p3));
        }
#pragma unroll
        for (int ms = 1; ms < 4; ms <<= 1) {
            sum0 += __shfl_xor_sync(0xffffffffu, sum0, ms);
            sum1 += __shfl_xor_sync(0xffffffffu, sum1, ms);
        }
        srow0 = srow0 * fac0 + sum0;
        srow1 = srow1 * fac1 + sum1;
#pragma unroll
        for (int nt = 0; nt < 16; nt++) {
            o[nt][0] *= fac0; o[nt][1] *= fac0;
            o[nt][2] *= fac1; o[nt][3] *= fac1;
        }

        // --- O += P V : warp-local rows; Ps written by this warp only ---
#pragma unroll
        for (int kc = 0; kc < 64; kc += 8) {
            unsigned af[4];
            af[0] = Ps[(wm + qr) * FPS_S + kc + qc];
            af[1] = Ps[(wm + qr + 8) * FPS_S + kc + qc];
            af[2] = Ps[(wm + qr) * FPS_S + kc + qc + 4];
            af[3] = Ps[(wm + qr + 8) * FPS_S + kc + qc + 4];
#pragma unroll
            for (int nt = 0; nt < 16; nt++) {
                unsigned bf[2];
                bf[0] = Vt[(nt * 8 + qr) * VT_S + kc + qc];
                bf[1] = Vt[(nt * 8 + qr) * VT_S + kc + qc + 4];
                mma_tf32(o[nt], af, bf);
            }
        }
    }

    // --- epilogue: normalize, write ctx at permuted rows ---
    const int b = bh >> 5;
    const int h = bh & 31;
    float inv0 = 1.0f / srow0, inv1 = 1.0f / srow1;
    int prow0 = g_iperm[b * LL + m0 + wm + qr];
    int prow1 = g_iperm[b * LL + m0 + wm + qr + 8];
    size_t base0 = (size_t)prow0 * HID + h * HD;
    size_t base1 = (size_t)prow1 * HID + h * HD;
#pragma unroll
    for (int nt = 0; nt < 16; nt++) {
        int cb = nt * 8 + 2 * qc;
        *(float2*)&g_ctx[base0 + cb] = make_float2(o[nt][0] * inv0, o[nt][1] * inv0);
        *(float2*)&g_ctx[base1 + cb] = make_float2(o[nt][2] * inv1, o[nt][3] * inv1);
    }
}

extern "C" void kernel_launch(void* const* d_in, const int* in_sizes, int n_in,
                              void* d_out, int out_size) {
    const float* hs   = (const float*)d_in[0];
    const int*   tt   = (const int*)d_in[1];
    const int*   pos  = (const int*)d_in[2];
    // d_in[3] = attention_mask (all zeros; reference math ignores it)
    const float* wvq  = (const float*)d_in[4];
    const float* wlq  = (const float*)d_in[5];
    const float* wvd  = (const float*)d_in[6];
    const float* wld  = (const float*)d_in[7];
    float* out = (float*)d_out;

    cudaFuncSetAttribute(flash_mma, cudaFuncAttributeMaxDynamicSharedMemorySize,
                         SMF_TOT * (int)sizeof(unsigned));

    prep_kernel<<<1024, 256>>>(tt);
    scan_kernel<<<1, 1024>>>();
    qkv_mma<<<dim3(MBLK, QKVN / 128), 256>>>(hs, wvq, wlq);
    rope_kernel<<<BH * LL, 128>>>(pos);
    flash_mma<<<dim3(LL / 128, BH), 256, SMF_TOT * (int)sizeof(unsigned)>>>();
    dense_mma<<<dim3(MBLK, HID / 128), 256>>>(out, wvd, wld);
}